// round 2
// baseline (speedup 1.0000x reference)
#include <cuda_runtime.h>
#include <cstddef>

#define N_ROWS 4096
#define CH     256
#define NC     1000

// ---- scratch (static device globals; no runtime allocation) ----
__device__ float g_invn[N_ROWS];
__device__ int   g_cls[N_ROWS];
__device__ float g_G[CH * CH];        // 65536 floats
__device__ float g_sums[NC * CH];     // 256000 floats
__device__ float g_counts[NC];        // 1000 floats

// ---------------------------------------------------------------
// K1: fused prep — blocks [0,512): per-row inv-norms (warp/row, float4)
//                  blocks [512,576): zero g_G      (64 blocks x 1024 floats)
//                  blocks [576,826): zero g_sums   (250 blocks x 1024 floats)
//                  block  826      : zero g_counts
// ---------------------------------------------------------------
__global__ void k_prep(const float* __restrict__ x) {
    int b = blockIdx.x;
    int tid = threadIdx.x;
    if (b < 512) {
        int warp = ((b << 8) + tid) >> 5;       // 0..4095
        int lane = tid & 31;
        const float4* p = (const float4*)(x + (size_t)warp * CH);
        float ss = 0.0f;
#pragma unroll
        for (int k = lane; k < 64; k += 32) {
            float4 v = p[k];
            ss += v.x * v.x + v.y * v.y + v.z * v.z + v.w * v.w;
        }
#pragma unroll
        for (int off = 16; off; off >>= 1)
            ss += __shfl_xor_sync(0xffffffffu, ss, off);
        if (lane == 0) g_invn[warp] = rsqrtf(ss);
    } else if (b < 576) {
        float4* g4 = (float4*)g_G;
        g4[(b - 512) * 256 + tid] = make_float4(0.f, 0.f, 0.f, 0.f);
    } else if (b < 826) {
        float4* s4 = (float4*)g_sums;
        s4[(b - 576) * 256 + tid] = make_float4(0.f, 0.f, 0.f, 0.f);
    } else {
        for (int i = tid; i < NC; i += 256) g_counts[i] = 0.0f;
    }
}

// ---------------------------------------------------------------
// K2: fused gram + argmax.
//   blocks [0,512): G = X^T D^{-1} X, 64x64 output tile, K-chunk 128,
//                   atomicAdd reduce (grid-equivalent (4,4,32))
//   blocks [512,4608): per-row argmax of logits + class counts
// Running both in one kernel lets argmax's memory-latency blocks fill
// gram's idle issue slots.
// ---------------------------------------------------------------
__global__ void k_cls_gram(const float* __restrict__ x,
                           const float* __restrict__ lg) {
    __shared__ float smem[2048];   // gram: As[16][64] | Bs[16][64]; argmax: sv/si
    int b = blockIdx.x;
    int tid = threadIdx.x;

    if (b < 512) {
        float* As = smem;            // [16][64] : Xn[k][i-tile]
        float* Bs = smem + 1024;     // [16][64] : X [k][j-tile]
        int bz = b >> 4;             // 0..31
        int rem = b & 15;
        int i0 = (rem >> 2) * 64, j0 = (rem & 3) * 64, k0 = bz * 128;
        int tx = tid & 15, ty = tid >> 4;

        float acc[4][4] = {};
        for (int kc = 0; kc < 128; kc += 16) {
#pragma unroll
            for (int l = 0; l < 4; l++) {
                int idx = tid + l * 256;          // 0..1023
                int kl = idx >> 6, col = idx & 63;
                int k = k0 + kc + kl;
                float inv = g_invn[k];
                As[kl * 64 + col] = x[(size_t)k * CH + i0 + col] * inv;
                Bs[kl * 64 + col] = x[(size_t)k * CH + j0 + col];
            }
            __syncthreads();
#pragma unroll
            for (int kl = 0; kl < 16; kl++) {
                float a[4], bb[4];
#pragma unroll
                for (int u = 0; u < 4; u++) a[u]  = As[kl * 64 + ty * 4 + u];
#pragma unroll
                for (int v = 0; v < 4; v++) bb[v] = Bs[kl * 64 + tx * 4 + v];
#pragma unroll
                for (int u = 0; u < 4; u++)
#pragma unroll
                    for (int v = 0; v < 4; v++)
                        acc[u][v] += a[u] * bb[v];
            }
            __syncthreads();
        }
#pragma unroll
        for (int u = 0; u < 4; u++)
#pragma unroll
            for (int v = 0; v < 4; v++)
                atomicAdd(&g_G[(i0 + ty * 4 + u) * CH + j0 + tx * 4 + v], acc[u][v]);
    } else {
        // ---- argmax over 1000 logits (== argmax of softmax) ----
        int row = b - 512;
        const float4* p = (const float4*)(lg + (size_t)row * NC);  // 250 float4
        float best = -3.4e38f;
        int   bi = 0;
        if (tid < 250) {
            float4 v = p[tid];
            int c = tid * 4;
            best = v.x; bi = c;
            if (v.y > best) { best = v.y; bi = c + 1; }
            if (v.z > best) { best = v.z; bi = c + 2; }
            if (v.w > best) { best = v.w; bi = c + 3; }
        }
        float* sv = smem;
        int*   si = (int*)(smem + 256);
        sv[tid] = best; si[tid] = bi;
        __syncthreads();
#pragma unroll
        for (int s = 128; s; s >>= 1) {
            if (tid < s) {
                float ov = sv[tid + s]; int oi = si[tid + s];
                if (ov > sv[tid] || (ov == sv[tid] && oi < si[tid])) {
                    sv[tid] = ov; si[tid] = oi;
                }
            }
            __syncthreads();
        }
        if (tid == 0) {
            g_cls[row] = si[0];
            atomicAdd(&g_counts[si[0]], 1.0f);
        }
    }
}

// ---------------------------------------------------------------
// K3: P = X @ G ; y = invn[row]*P + x ; atomic scatter into class sums
// grid (128,4), block 256; 32(rows) x 64(cols) tile, k=256
// ---------------------------------------------------------------
__global__ void k_agg(const float* __restrict__ x) {
    __shared__ float As[32][17];  // x[row-tile][k-chunk] (padded)
    __shared__ float Bs[16][64];  // G[k][col-tile]
    int r0 = blockIdx.x * 32, c0 = blockIdx.y * 64;
    int tid = threadIdx.x;
    int tx = tid & 15, ty = tid >> 4;

    float acc[2][4] = {};
    for (int k0 = 0; k0 < 256; k0 += 16) {
#pragma unroll
        for (int l = 0; l < 2; l++) {
            int idx = tid + l * 256;          // 0..511
            int r = idx >> 4, kl = idx & 15;
            As[r][kl] = x[(size_t)(r0 + r) * CH + k0 + kl];
        }
#pragma unroll
        for (int l = 0; l < 4; l++) {
            int idx = tid + l * 256;          // 0..1023
            int kl = idx >> 6, col = idx & 63;
            Bs[kl][col] = g_G[(k0 + kl) * CH + c0 + col];
        }
        __syncthreads();
#pragma unroll
        for (int kl = 0; kl < 16; kl++) {
            float a[2], bb[4];
#pragma unroll
            for (int u = 0; u < 2; u++) a[u]  = As[ty * 2 + u][kl];
#pragma unroll
            for (int v = 0; v < 4; v++) bb[v] = Bs[kl][tx * 4 + v];
#pragma unroll
            for (int u = 0; u < 2; u++)
#pragma unroll
                for (int v = 0; v < 4; v++)
                    acc[u][v] += a[u] * bb[v];
        }
        __syncthreads();
    }
#pragma unroll
    for (int u = 0; u < 2; u++) {
        int row = r0 + ty * 2 + u;
        float inv = g_invn[row];
        int cls = g_cls[row];
#pragma unroll
        for (int v = 0; v < 4; v++) {
            int col = c0 + tx * 4 + v;
            float y = acc[u][v] * inv + x[(size_t)row * CH + col];
            atomicAdd(&g_sums[cls * CH + col], y);
        }
    }
}

// ---------------------------------------------------------------
// K4: prototypes = counts>0 ? sums/counts : 0  -> d_out[0:NC*CH]
// ---------------------------------------------------------------
__global__ void k_proto(float* __restrict__ proto) {
    int c = blockIdx.x;
    int d = threadIdx.x;
    float cnt = g_counts[c];
    float v = 0.0f;
    if (cnt > 0.0f) v = g_sums[c * CH + d] / fmaxf(cnt, 1.0f);
    proto[c * CH + d] = v;
}

// ---------------------------------------------------------------
// K5: inter[i][j][:] = proto[j] - proto[i]   (1.02 GB, write-bound)
// 16x16 (i,j) tiles, proto rows cached in smem, float4 streaming stores
// ---------------------------------------------------------------
__global__ void k_inter(const float* __restrict__ proto, float* __restrict__ inter) {
    __shared__ float4 pi[16][64];
    __shared__ float4 pj[16][64];
    int i0 = blockIdx.y * 16, j0 = blockIdx.x * 16;
    int tid = threadIdx.x;               // 256 threads

    const float4* p4 = (const float4*)proto;
#pragma unroll
    for (int l = 0; l < 4; l++) {
        int idx = tid + l * 256;         // 0..1023
        int r = idx >> 6, d = idx & 63;
        int gi = i0 + r, gj = j0 + r;
        pi[r][d] = (gi < NC) ? p4[gi * 64 + d] : make_float4(0.f, 0.f, 0.f, 0.f);
        pj[r][d] = (gj < NC) ? p4[gj * 64 + d] : make_float4(0.f, 0.f, 0.f, 0.f);
    }
    __syncthreads();

    int d = tid & 63;
    int p0 = tid >> 6;                   // 0..3
    float4* o4 = (float4*)inter;
#pragma unroll 4
    for (int p = p0; p < 256; p += 4) {
        int il = p >> 4, jl = p & 15;
        int i = i0 + il, j = j0 + jl;
        if (i < NC && j < NC) {
            float4 a = pj[jl][d];
            float4 b = pi[il][d];
            float4 v = make_float4(a.x - b.x, a.y - b.y, a.z - b.z, a.w - b.w);
            __stcs(&o4[((size_t)i * NC + j) * 64 + d], v);
        }
    }
}

// ---------------------------------------------------------------
extern "C" void kernel_launch(void* const* d_in, const int* in_sizes, int n_in,
                              void* d_out, int out_size) {
    const float* x  = (const float*)d_in[0];   // [4096, 256]
    const float* lg = (const float*)d_in[1];   // [4096, 1000]
    float* out   = (float*)d_out;
    float* proto = out;                         // [1000, 256]
    float* inter = out + (size_t)NC * CH;       // [1000, 1000, 256]

    k_prep    <<<827, 256>>>(x);
    k_cls_gram<<<4608, 256>>>(x, lg);
    k_agg     <<<dim3(128, 4), 256>>>(x);
    k_proto   <<<NC, CH>>>(proto);
    k_inter   <<<dim3(63, 63), 256>>>(proto, inter);
}

// round 3
// speedup vs baseline: 1.0400x; 1.0400x over previous
#include <cuda_runtime.h>
#include <cstddef>

#define N_ROWS 4096
#define CH     256
#define NC     1000

// ---- scratch (static device globals; no runtime allocation) ----
__device__ float g_invn[N_ROWS];
__device__ float g_G[CH * CH];        // gram:  G = X^T D^-1 X (symmetric)
__device__ float g_s[NC * CH];        // per-class sum of invn_r * x_r
__device__ float g_t[NC * CH];        // per-class sum of x_r
__device__ float g_counts[NC];

// ---------------------------------------------------------------
// K1: prep — norms + zero accumulators
//  b in [0,512)    : per-row inv-norms (warp/row, float4)
//  b in [512,576)  : zero g_G      (64 x 1024 floats)
//  b in [576,826)  : zero g_s      (250 x 1024)
//  b in [826,1076) : zero g_t      (250 x 1024)
//  b == 1076       : zero g_counts
// ---------------------------------------------------------------
__global__ void k_prep(const float* __restrict__ x) {
    int b = blockIdx.x;
    int tid = threadIdx.x;
    if (b < 512) {
        int warp = ((b << 8) + tid) >> 5;       // 0..4095
        int lane = tid & 31;
        const float4* p = (const float4*)(x + (size_t)warp * CH);
        float ss = 0.0f;
#pragma unroll
        for (int k = lane; k < 64; k += 32) {
            float4 v = p[k];
            ss += v.x * v.x + v.y * v.y + v.z * v.z + v.w * v.w;
        }
#pragma unroll
        for (int off = 16; off; off >>= 1)
            ss += __shfl_xor_sync(0xffffffffu, ss, off);
        if (lane == 0) g_invn[warp] = rsqrtf(ss);
    } else if (b < 576) {
        ((float4*)g_G)[(b - 512) * 256 + tid] = make_float4(0.f, 0.f, 0.f, 0.f);
    } else if (b < 826) {
        ((float4*)g_s)[(b - 576) * 256 + tid] = make_float4(0.f, 0.f, 0.f, 0.f);
    } else if (b < 1076) {
        ((float4*)g_t)[(b - 826) * 256 + tid] = make_float4(0.f, 0.f, 0.f, 0.f);
    } else {
        for (int i = tid; i < NC; i += 256) g_counts[i] = 0.0f;
    }
}

// ---------------------------------------------------------------
// K2: fused symmetric gram + (argmax -> class scatter).
//  b in [0,160): gram, upper-triangle 64x64 tiles only (10 tiles x 16 K-splits
//                of 256), mirrored atomic writes for off-diagonal tiles.
//  b in [160, 160+4096): per-row argmax of logits, then scatter-add the row
//                into g_s (invn-weighted) and g_t, bump g_counts.
// ---------------------------------------------------------------
__global__ void k_fused(const float* __restrict__ x,
                        const float* __restrict__ lg) {
    __shared__ float smem[2048];
    int b = blockIdx.x;
    int tid = threadIdx.x;

    if (b < 160) {
        const int ti_lut[10] = {0,0,0,0,1,1,1,2,2,3};
        const int tj_lut[10] = {0,1,2,3,1,2,3,2,3,3};
        float* As = smem;            // [16][64] : Xn[k][i-tile] (invn applied)
        float* Bs = smem + 1024;     // [16][64] : X [k][j-tile]
        int tile = b >> 4;           // 0..9
        int k0 = (b & 15) * 256;
        int i0 = ti_lut[tile] * 64, j0 = tj_lut[tile] * 64;
        int tx = tid & 15, ty = tid >> 4;

        float acc[4][4] = {};
        for (int kc = 0; kc < 256; kc += 16) {
#pragma unroll
            for (int l = 0; l < 4; l++) {
                int idx = tid + l * 256;          // 0..1023
                int kl = idx >> 6, col = idx & 63;
                int k = k0 + kc + kl;
                float inv = g_invn[k];
                As[kl * 64 + col] = x[(size_t)k * CH + i0 + col] * inv;
                Bs[kl * 64 + col] = x[(size_t)k * CH + j0 + col];
            }
            __syncthreads();
#pragma unroll
            for (int kl = 0; kl < 16; kl++) {
                float a[4], bb[4];
#pragma unroll
                for (int u = 0; u < 4; u++) a[u]  = As[kl * 64 + ty * 4 + u];
#pragma unroll
                for (int v = 0; v < 4; v++) bb[v] = Bs[kl * 64 + tx * 4 + v];
#pragma unroll
                for (int u = 0; u < 4; u++)
#pragma unroll
                    for (int v = 0; v < 4; v++)
                        acc[u][v] += a[u] * bb[v];
            }
            __syncthreads();
        }
        bool offdiag = (i0 != j0);
#pragma unroll
        for (int u = 0; u < 4; u++) {
            int i = i0 + ty * 4 + u;
#pragma unroll
            for (int v = 0; v < 4; v++) {
                int j = j0 + tx * 4 + v;
                atomicAdd(&g_G[i * CH + j], acc[u][v]);
                if (offdiag) atomicAdd(&g_G[j * CH + i], acc[u][v]);
            }
        }
    } else {
        // ---- argmax over 1000 logits + scatter-add of this row ----
        int row = b - 160;
        const float4* p = (const float4*)(lg + (size_t)row * NC);  // 250 float4
        float best = -3.4e38f;
        int   bi = 0;
        if (tid < 250) {
            float4 v = p[tid];
            int c = tid * 4;
            best = v.x; bi = c;
            if (v.y > best) { best = v.y; bi = c + 1; }
            if (v.z > best) { best = v.z; bi = c + 2; }
            if (v.w > best) { best = v.w; bi = c + 3; }
        }
        float* sv = smem;
        int*   si = (int*)(smem + 256);
        sv[tid] = best; si[tid] = bi;
        __syncthreads();
#pragma unroll
        for (int s = 128; s; s >>= 1) {
            if (tid < s) {
                float ov = sv[tid + s]; int oi = si[tid + s];
                if (ov > sv[tid] || (ov == sv[tid] && oi < si[tid])) {
                    sv[tid] = ov; si[tid] = oi;
                }
            }
            __syncthreads();
        }
        int cls = si[0];
        float inv = g_invn[row];
        float xv  = x[(size_t)row * CH + tid];
        atomicAdd(&g_s[cls * CH + tid], xv * inv);
        atomicAdd(&g_t[cls * CH + tid], xv);
        if (tid == 0) atomicAdd(&g_counts[cls], 1.0f);
    }
}

// ---------------------------------------------------------------
// K3: prototypes: proto_c = (s_c @ G + t_c) / count  (0 if count==0)
// 125 blocks x 8 classes, 256 threads (thread = output column)
// ---------------------------------------------------------------
__global__ void k_proto(float* __restrict__ proto) {
    __shared__ float s_sm[8 * 256];
    int c0 = blockIdx.x * 8;
    int tid = threadIdx.x;

#pragma unroll
    for (int l = 0; l < 8; l++)
        s_sm[l * 256 + tid] = g_s[(size_t)(c0 + l) * CH + tid];
    __syncthreads();

    float acc[8] = {};
#pragma unroll 4
    for (int k = 0; k < 256; k++) {
        float gk = g_G[k * CH + tid];
#pragma unroll
        for (int c = 0; c < 8; c++)
            acc[c] += s_sm[c * 256 + k] * gk;
    }
#pragma unroll
    for (int c = 0; c < 8; c++) {
        int cls = c0 + c;
        float cnt = g_counts[cls];
        float v = 0.0f;
        if (cnt > 0.0f)
            v = (acc[c] + g_t[(size_t)cls * CH + tid]) / cnt;
        proto[(size_t)cls * CH + tid] = v;
    }
}

// ---------------------------------------------------------------
// K4: inter[i][j][:] = proto[j] - proto[i]   (1.02 GB, write-bound)
// 16x16 (i,j) tiles, proto rows cached in smem, float4 streaming stores
// ---------------------------------------------------------------
__global__ void k_inter(const float* __restrict__ proto, float* __restrict__ inter) {
    __shared__ float4 pi[16][64];
    __shared__ float4 pj[16][64];
    int i0 = blockIdx.y * 16, j0 = blockIdx.x * 16;
    int tid = threadIdx.x;               // 256 threads

    const float4* p4 = (const float4*)proto;
#pragma unroll
    for (int l = 0; l < 4; l++) {
        int idx = tid + l * 256;         // 0..1023
        int r = idx >> 6, d = idx & 63;
        int gi = i0 + r, gj = j0 + r;
        pi[r][d] = (gi < NC) ? p4[gi * 64 + d] : make_float4(0.f, 0.f, 0.f, 0.f);
        pj[r][d] = (gj < NC) ? p4[gj * 64 + d] : make_float4(0.f, 0.f, 0.f, 0.f);
    }
    __syncthreads();

    int d = tid & 63;
    int p0 = tid >> 6;                   // 0..3
    float4* o4 = (float4*)inter;
#pragma unroll 4
    for (int p = p0; p < 256; p += 4) {
        int il = p >> 4, jl = p & 15;
        int i = i0 + il, j = j0 + jl;
        if (i < NC && j < NC) {
            float4 a = pj[jl][d];
            float4 b = pi[il][d];
            float4 v = make_float4(a.x - b.x, a.y - b.y, a.z - b.z, a.w - b.w);
            __stcs(&o4[((size_t)i * NC + j) * 64 + d], v);
        }
    }
}

// ---------------------------------------------------------------
extern "C" void kernel_launch(void* const* d_in, const int* in_sizes, int n_in,
                              void* d_out, int out_size) {
    const float* x  = (const float*)d_in[0];   // [4096, 256]
    const float* lg = (const float*)d_in[1];   // [4096, 1000]
    float* out   = (float*)d_out;
    float* proto = out;                         // [1000, 256]
    float* inter = out + (size_t)NC * CH;       // [1000, 1000, 256]

    k_prep <<<1077, 256>>>(x);
    k_fused<<<160 + N_ROWS, 256>>>(x, lg);
    k_proto<<<125, 256>>>(proto);
    k_inter<<<dim3(63, 63), 256>>>(proto, inter);
}